// round 16
// baseline (speedup 1.0000x reference)
#include <cuda_runtime.h>
#include <cuda_bf16.h>
#include <cstdint>

#define LOG2E 1.4426950408889634f
#define NP  16384
#define NT  256      // j-tiles of 64
#define NWG 1024     // i row-groups of 16
#define NSL 18       // j-slices: 4x15 + 14x14 = 256

// ---- static device scratch (no allocation) ----
__device__ uint32_t g_Xf[NWG * 32 * 16];  // a-frag image
__device__ uint32_t g_Yf[NT * 2048];      // b-frag image (GEMM1)
__device__ uint32_t g_Bf[NT * 1024];      // b-frag image (GEMM2)
__device__ float g_cxn[NP];
__device__ float g_cyn[NP];
__device__ float g_Op[NSL * NP * 16];     // per-slice fp32 partials (18 MB)

// ---- helpers ----
__device__ __forceinline__ uint32_t smem_u32(const void* p) {
    uint32_t a;
    asm("{ .reg .u64 t; cvta.to.shared.u64 t, %1; cvt.u32.u64 %0, t; }" : "=r"(a) : "l"(p));
    return a;
}
__device__ __forceinline__ void cp16(uint32_t d, const void* s) {
    asm volatile("cp.async.cg.shared.global [%0], [%1], 16;" :: "r"(d), "l"(s));
}
#define CP_COMMIT() asm volatile("cp.async.commit_group;" ::: "memory")
#define CP_WAIT0()  asm volatile("cp.async.wait_group 0;" ::: "memory")

__device__ __forceinline__ void mma_bf16(float* d, const uint32_t* a, uint32_t b0, uint32_t b1) {
    asm volatile("mma.sync.aligned.m16n8k16.row.col.f32.bf16.bf16.f32 "
                 "{%0,%1,%2,%3},{%4,%5,%6,%7},{%8,%9},{%0,%1,%2,%3};"
                 : "+f"(d[0]), "+f"(d[1]), "+f"(d[2]), "+f"(d[3])
                 : "r"(a[0]), "r"(a[1]), "r"(a[2]), "r"(a[3]), "r"(b0), "r"(b1));
}
__device__ __forceinline__ float ex2f(float a) {
    float r; asm("ex2.approx.ftz.f32 %0, %1;" : "=f"(r) : "f"(a)); return r;
}
__device__ __forceinline__ uint32_t pk2(float lo, float hi) {
    __nv_bfloat162 h = __float22bfloat162_rn(make_float2(lo, hi));
    return *(uint32_t*)&h;
}
__device__ __forceinline__ float bflo(uint32_t u) { return __uint_as_float(u << 16); }
__device__ __forceinline__ float bfhi(uint32_t u) { return __uint_as_float(u & 0xffff0000u); }
__device__ __forceinline__ uint32_t pk_split(float a, float b, int low) {
    float ah = __bfloat162float(__float2bfloat16(a));
    float bh = __bfloat162float(__float2bfloat16(b));
    return low ? pk2(a - ah, b - bh) : pk2(ah, bh);
}

// ================= fused prep kernel: ONE task per thread =================
__global__ void prep_all(const float* __restrict__ ls, const float* __restrict__ x,
                         const float* __restrict__ y, const float* __restrict__ b) {
    int u = blockIdx.x * 128 + threadIdx.x;
    int l = u & 31;
    const float cneg = -ls[0] * LOG2E;

    if (u < 32768) {
        // ---- X a-frags ----
        int t = u;
        int wg = t >> 5;
        int r0 = wg * 16 + (l >> 2), r1 = r0 + 8;
        int c = 2 * (l & 3);
        const float* x0 = x + (size_t)r0 * 32;
        const float* x1 = x + (size_t)r1 * 32;
        float v0[8], v1[8], n0 = 0.f, n1 = 0.f;
#pragma unroll
        for (int kf = 0; kf < 2; kf++)
#pragma unroll
            for (int h = 0; h < 2; h++)
#pragma unroll
                for (int e = 0; e < 2; e++) {
                    int idx = kf * 4 + h * 2 + e;
                    int col = kf * 16 + h * 8 + c + e;
                    v0[idx] = x0[col]; v1[idx] = x1[col];
                    n0 += v0[idx] * v0[idx];
                    n1 += v1[idx] * v1[idx];
                }
        n0 += __shfl_xor_sync(0xffffffffu, n0, 1); n0 += __shfl_xor_sync(0xffffffffu, n0, 2);
        n1 += __shfl_xor_sync(0xffffffffu, n1, 1); n1 += __shfl_xor_sync(0xffffffffu, n1, 2);
        if ((l & 3) == 0) { g_cxn[r0] = cneg * n0; g_cxn[r1] = cneg * n1; }

        uint32_t o[16];
#pragma unroll
        for (int s = 0; s < 2; s++)
#pragma unroll
            for (int kf = 0; kf < 2; kf++)
#pragma unroll
                for (int h = 0; h < 2; h++) {
                    o[s * 8 + kf * 4 + h * 2 + 0] = pk_split(v0[kf * 4 + h * 2], v0[kf * 4 + h * 2 + 1], s);
                    o[s * 8 + kf * 4 + h * 2 + 1] = pk_split(v1[kf * 4 + h * 2], v1[kf * 4 + h * 2 + 1], s);
                }
        uint4* dst = (uint4*)(g_Xf + (size_t)t * 16);
#pragma unroll
        for (int q = 0; q < 4; q++)
            dst[q] = make_uint4(o[4 * q], o[4 * q + 1], o[4 * q + 2], o[4 * q + 3]);
    } else if (u < 98304) {
        // ---- Y b-frags ----
        int t = u - 32768;
        int tn = t >> 5;
        int j = tn * 8 + (l >> 2);
        int c = 2 * (l & 3);
        const float* yr = y + (size_t)j * 32;
        float v[8], n = 0.f;
#pragma unroll
        for (int kf = 0; kf < 2; kf++)
#pragma unroll
            for (int h = 0; h < 2; h++)
#pragma unroll
                for (int e = 0; e < 2; e++) {
                    int idx = kf * 4 + h * 2 + e;
                    v[idx] = yr[kf * 16 + h * 8 + c + e];
                    n += v[idx] * v[idx];
                }
        n += __shfl_xor_sync(0xffffffffu, n, 1); n += __shfl_xor_sync(0xffffffffu, n, 2);
        if ((l & 3) == 0) g_cyn[j] = cneg * n;

        uint32_t o[8];
#pragma unroll
        for (int s = 0; s < 2; s++)
#pragma unroll
            for (int kf = 0; kf < 2; kf++)
#pragma unroll
                for (int h = 0; h < 2; h++)
                    o[s * 4 + kf * 2 + h] = pk_split(v[kf * 4 + h * 2], v[kf * 4 + h * 2 + 1], s);
        uint4* dst = (uint4*)(g_Yf + (size_t)tn * 256 + l * 8);
        dst[0] = make_uint4(o[0], o[1], o[2], o[3]);
        dst[1] = make_uint4(o[4], o[5], o[6], o[7]);
    } else {
        // ---- B b-frags ----
        int t = u - 98304;
        int uu = t >> 5;
        int tile = uu >> 3, fp = uu & 7, kf = fp >> 1, nb2 = fp & 1;
        int c = nb2 * 8 + (l >> 2);
        int jb = tile * 64 + kf * 16 + 2 * (l & 3);
        float p0 = b[(size_t)jb * 16 + c];
        float p1 = b[(size_t)(jb + 1) * 16 + c];
        float p2 = b[(size_t)(jb + 8) * 16 + c];
        float p3 = b[(size_t)(jb + 9) * 16 + c];
        uint32_t h0 = pk_split(p0, p1, 0), h1 = pk_split(p2, p3, 0);
        uint32_t l0 = pk_split(p0, p1, 1), l1 = pk_split(p2, p3, 1);
        *(uint4*)(g_Bf + (size_t)tile * 1024 + fp * 128 + l * 4) = make_uint4(h0, h1, l0, l1);
    }
}

// ================= main kernel: 4 warps x 32 i-rows = 128 i-rows/CTA, 6 CTAs/SM =================
#define SMEM_BYTES 25088

__device__ __forceinline__ void issue_loads(uint32_t smb, int tile, int buf, int tid) {
    const char* gy = (const char*)g_Yf + (size_t)tile * 8192;
    uint32_t dy = smb + buf * 8192;
#pragma unroll
    for (int k = 0; k < 4; k++) cp16(dy + (tid + k * 128) * 16, gy + (size_t)(tid + k * 128) * 16);
    const char* gb = (const char*)g_Bf + (size_t)tile * 4096;
    uint32_t db = smb + 16384 + buf * 4096;
#pragma unroll
    for (int k = 0; k < 2; k++) cp16(db + (tid + k * 128) * 16, gb + (size_t)(tid + k * 128) * 16);
    if (tid < 16) cp16(smb + 24576 + buf * 256 + tid * 16, (const char*)(g_cyn + tile * 64) + tid * 16);
}

__global__ void __launch_bounds__(128, 6)
rbf_main(const float* __restrict__ ls) {
    __shared__ __align__(16) char sm[SMEM_BYTES];
    const uint32_t smb = smem_u32(sm);
    const int tid = threadIdx.x, w = tid >> 5, l = tid & 31;
    const int bidx = blockIdx.x;           // i-block 0..127 (128 rows each)
    const int sl = blockIdx.y;             // j-slice 0..17
    const int tstart = (sl < 4) ? 15 * sl : (60 + 14 * (sl - 4));
    const int tcnt = (sl < 4) ? 15 : 14;
    const int ig = bidx * 128 + w * 32;    // first i-row of this warp's 32

    uint32_t xfA[16], xfB[16];
    {
        const uint4* pA = (const uint4*)(g_Xf + ((size_t)(bidx * 8 + 2 * w) * 32 + l) * 16);
        const uint4* pB = (const uint4*)(g_Xf + ((size_t)(bidx * 8 + 2 * w + 1) * 32 + l) * 16);
#pragma unroll
        for (int q = 0; q < 4; q++) { *(uint4*)(xfA + 4 * q) = pA[q]; *(uint4*)(xfB + 4 * q) = pB[q]; }
    }
    const float cxnA0 = g_cxn[ig + (l >> 2)];
    const float cxnA1 = g_cxn[ig + (l >> 2) + 8];
    const float cxnB0 = g_cxn[ig + (l >> 2) + 16];
    const float cxnB1 = g_cxn[ig + (l >> 2) + 24];
    const float C2 = 2.f * __ldg(ls) * LOG2E;

    float o0A[4] = {0.f, 0.f, 0.f, 0.f}, o1A[4] = {0.f, 0.f, 0.f, 0.f};
    float o0B[4] = {0.f, 0.f, 0.f, 0.f}, o1B[4] = {0.f, 0.f, 0.f, 0.f};

    issue_loads(smb, tstart, 0, tid);
    CP_COMMIT();

    for (int tt = 0; tt < tcnt; tt++) {
        CP_WAIT0();
        __syncthreads();
        if (tt + 1 < tcnt) { issue_loads(smb, tstart + tt + 1, (tt + 1) & 1, tid); CP_COMMIT(); }
        const int buf = tt & 1;
        const char* syb = sm + buf * 8192;
        const char* sbb = sm + 16384 + buf * 4096;
        const char* scy = sm + 24576 + buf * 256;

#pragma unroll
        for (int g = 0; g < 4; g++) {
            uint32_t wahA[4], walA[4], wahB[4], walB[4];
            const char* yb0 = syb + (g * 2) * 1024 + l * 32;
            const char* yb1 = syb + (g * 2 + 1) * 1024 + l * 32;
            uint4 y00 = *(const uint4*)yb0;
            uint4 y01 = *(const uint4*)(yb0 + 16);
            uint4 y10 = *(const uint4*)yb1;
            uint4 y11 = *(const uint4*)(yb1 + 16);

            // ---- GEMM1 burst: 24 MMAs, 4 chains (sA,sB,tA,tB) round-robin ----
            float sA[4] = {0.f, 0.f, 0.f, 0.f}, sB[4] = {0.f, 0.f, 0.f, 0.f};
            float tA[4] = {0.f, 0.f, 0.f, 0.f}, tB[4] = {0.f, 0.f, 0.f, 0.f};
            mma_bf16(sA, xfA + 0,  y00.x, y00.y);
            mma_bf16(sB, xfB + 0,  y00.x, y00.y);
            mma_bf16(tA, xfA + 0,  y10.x, y10.y);
            mma_bf16(tB, xfB + 0,  y10.x, y10.y);
            mma_bf16(sA, xfA + 4,  y00.z, y00.w);
            mma_bf16(sB, xfB + 4,  y00.z, y00.w);
            mma_bf16(tA, xfA + 4,  y10.z, y10.w);
            mma_bf16(tB, xfB + 4,  y10.z, y10.w);
            mma_bf16(sA, xfA + 0,  y01.x, y01.y);
            mma_bf16(sB, xfB + 0,  y01.x, y01.y);
            mma_bf16(tA, xfA + 0,  y11.x, y11.y);
            mma_bf16(tB, xfB + 0,  y11.x, y11.y);
            mma_bf16(sA, xfA + 4,  y01.z, y01.w);
            mma_bf16(sB, xfB + 4,  y01.z, y01.w);
            mma_bf16(tA, xfA + 4,  y11.z, y11.w);
            mma_bf16(tB, xfB + 4,  y11.z, y11.w);
            mma_bf16(sA, xfA + 8,  y00.x, y00.y);
            mma_bf16(sB, xfB + 8,  y00.x, y00.y);
            mma_bf16(tA, xfA + 8,  y10.x, y10.y);
            mma_bf16(tB, xfB + 8,  y10.x, y10.y);
            mma_bf16(sA, xfA + 12, y00.z, y00.w);
            mma_bf16(sB, xfB + 12, y00.z, y00.w);
            mma_bf16(tA, xfA + 12, y10.z, y10.w);
            mma_bf16(tB, xfB + 12, y10.z, y10.w);

            // ---- epilogue h0 ----
            {
                float2 cy = *(const float2*)(scy + (g * 2) * 32 + (l & 3) * 8);
                float w0 = ex2f(fminf(fmaf(C2, sA[0], cxnA0 + cy.x), 0.f));
                float w1 = ex2f(fminf(fmaf(C2, sA[1], cxnA0 + cy.y), 0.f));
                float w2 = ex2f(fminf(fmaf(C2, sA[2], cxnA1 + cy.x), 0.f));
                float w3 = ex2f(fminf(fmaf(C2, sA[3], cxnA1 + cy.y), 0.f));
                uint32_t h01 = pk2(w0, w1), h23 = pk2(w2, w3);
                wahA[0] = h01; wahA[1] = h23;
                walA[0] = pk2(w0 - bflo(h01), w1 - bfhi(h01));
                walA[1] = pk2(w2 - bflo(h23), w3 - bfhi(h23));
                float v0 = ex2f(fminf(fmaf(C2, sB[0], cxnB0 + cy.x), 0.f));
                float v1 = ex2f(fminf(fmaf(C2, sB[1], cxnB0 + cy.y), 0.f));
                float v2 = ex2f(fminf(fmaf(C2, sB[2], cxnB1 + cy.x), 0.f));
                float v3 = ex2f(fminf(fmaf(C2, sB[3], cxnB1 + cy.y), 0.f));
                uint32_t g01 = pk2(v0, v1), g23 = pk2(v2, v3);
                wahB[0] = g01; wahB[1] = g23;
                walB[0] = pk2(v0 - bflo(g01), v1 - bfhi(g01));
                walB[1] = pk2(v2 - bflo(g23), v3 - bfhi(g23));
            }
            // ---- epilogue h1 ----
            {
                float2 cy = *(const float2*)(scy + (g * 2 + 1) * 32 + (l & 3) * 8);
                float w0 = ex2f(fminf(fmaf(C2, tA[0], cxnA0 + cy.x), 0.f));
                float w1 = ex2f(fminf(fmaf(C2, tA[1], cxnA0 + cy.y), 0.f));
                float w2 = ex2f(fminf(fmaf(C2, tA[2], cxnA1 + cy.x), 0.f));
                float w3 = ex2f(fminf(fmaf(C2, tA[3], cxnA1 + cy.y), 0.f));
                uint32_t h01 = pk2(w0, w1), h23 = pk2(w2, w3);
                wahA[2] = h01; wahA[3] = h23;
                walA[2] = pk2(w0 - bflo(h01), w1 - bfhi(h01));
                walA[3] = pk2(w2 - bflo(h23), w3 - bfhi(h23));
                float v0 = ex2f(fminf(fmaf(C2, tB[0], cxnB0 + cy.x), 0.f));
                float v1 = ex2f(fminf(fmaf(C2, tB[1], cxnB0 + cy.y), 0.f));
                float v2 = ex2f(fminf(fmaf(C2, tB[2], cxnB1 + cy.x), 0.f));
                float v3 = ex2f(fminf(fmaf(C2, tB[3], cxnB1 + cy.y), 0.f));
                uint32_t g01 = pk2(v0, v1), g23 = pk2(v2, v3);
                wahB[2] = g01; wahB[3] = g23;
                walB[2] = pk2(v0 - bflo(g01), v1 - bfhi(g01));
                walB[3] = pk2(v2 - bflo(g23), v3 - bfhi(g23));
            }
            // ---- GEMM2: 4 accumulator chains round-robin ----
            uint4 b0 = *(const uint4*)(sbb + (g * 2) * 512 + l * 16);
            uint4 b1 = *(const uint4*)(sbb + (g * 2 + 1) * 512 + l * 16);
            mma_bf16(o0A, wahA, b0.x, b0.y);
            mma_bf16(o0B, wahB, b0.x, b0.y);
            mma_bf16(o1A, wahA, b1.x, b1.y);
            mma_bf16(o1B, wahB, b1.x, b1.y);
            mma_bf16(o0A, wahA, b0.z, b0.w);
            mma_bf16(o0B, wahB, b0.z, b0.w);
            mma_bf16(o1A, wahA, b1.z, b1.w);
            mma_bf16(o1B, wahB, b1.z, b1.w);
            mma_bf16(o0A, walA, b0.x, b0.y);
            mma_bf16(o0B, walB, b0.x, b0.y);
            mma_bf16(o1A, walA, b1.x, b1.y);
            mma_bf16(o1B, walB, b1.x, b1.y);
        }
    }

    // partial write: slice-local buffer
    float* op = g_Op + (size_t)sl * (NP * 16);
    const int cb = 2 * (l & 3);
    const int rA = ig + (l >> 2), rB = rA + 16;
    *(float2*)(op + (size_t)rA * 16 + cb)            = make_float2(o0A[0], o0A[1]);
    *(float2*)(op + (size_t)rA * 16 + 8 + cb)        = make_float2(o1A[0], o1A[1]);
    *(float2*)(op + (size_t)(rA + 8) * 16 + cb)      = make_float2(o0A[2], o0A[3]);
    *(float2*)(op + (size_t)(rA + 8) * 16 + 8 + cb)  = make_float2(o1A[2], o1A[3]);
    *(float2*)(op + (size_t)rB * 16 + cb)            = make_float2(o0B[0], o0B[1]);
    *(float2*)(op + (size_t)rB * 16 + 8 + cb)        = make_float2(o1B[0], o1B[1]);
    *(float2*)(op + (size_t)(rB + 8) * 16 + cb)      = make_float2(o0B[2], o0B[3]);
    *(float2*)(op + (size_t)(rB + 8) * 16 + 8 + cb)  = make_float2(o1B[2], o1B[3]);
}

// ================= deterministic slice reduction =================
__global__ void reduce_k(float* __restrict__ out) {
    int idx = blockIdx.x * 256 + threadIdx.x;
    float4 o = ((const float4*)g_Op)[idx];
#pragma unroll
    for (int s = 1; s < NSL; s++) {
        float4 v = ((const float4*)(g_Op + (size_t)s * NP * 16))[idx];
        o.x += v.x; o.y += v.y; o.z += v.z; o.w += v.w;   // fixed slice order
    }
    ((float4*)out)[idx] = o;
}

extern "C" void kernel_launch(void* const* d_in, const int* in_sizes, int n_in,
                              void* d_out, int out_size) {
    const float* ls = (const float*)d_in[0];
    const float* x  = (const float*)d_in[1];
    const float* y  = (const float*)d_in[2];
    const float* b  = (const float*)d_in[3];
    float* out = (float*)d_out;

    prep_all<<<1280, 128>>>(ls, x, y, b);
    rbf_main<<<dim3(128, NSL), 128>>>(ls);
    reduce_k<<<256, 256>>>(out);
}

// round 17
// speedup vs baseline: 1.0877x; 1.0877x over previous
#include <cuda_runtime.h>
#include <cuda_bf16.h>
#include <cstdint>

#define LOG2E 1.4426950408889634f
#define NP  16384
#define NT  256      // j-tiles of 64
#define NWG 1024     // i row-groups of 16
#define NSL 18       // j-slices: 4x15 + 14x14 = 256

// ---- static device scratch (no allocation) ----
__device__ uint32_t g_Xf[NWG * 32 * 16];  // a-frag image
__device__ uint32_t g_Yf[NT * 2048];      // b-frag image (GEMM1)
__device__ uint32_t g_Bf[NT * 1024];      // b-frag image (GEMM2)
__device__ float g_cxn[NP];
__device__ float g_cyn[NP];
__device__ float g_Op[NSL * NP * 16];     // per-slice fp32 partials (18 MB)

// ---- helpers ----
__device__ __forceinline__ uint32_t smem_u32(const void* p) {
    uint32_t a;
    asm("{ .reg .u64 t; cvta.to.shared.u64 t, %1; cvt.u32.u64 %0, t; }" : "=r"(a) : "l"(p));
    return a;
}
__device__ __forceinline__ void cp16(uint32_t d, const void* s) {
    asm volatile("cp.async.cg.shared.global [%0], [%1], 16;" :: "r"(d), "l"(s));
}
#define CP_COMMIT() asm volatile("cp.async.commit_group;" ::: "memory")
#define CP_WAIT0()  asm volatile("cp.async.wait_group 0;" ::: "memory")

__device__ __forceinline__ void mma_bf16(float* d, const uint32_t* a, uint32_t b0, uint32_t b1) {
    asm volatile("mma.sync.aligned.m16n8k16.row.col.f32.bf16.bf16.f32 "
                 "{%0,%1,%2,%3},{%4,%5,%6,%7},{%8,%9},{%0,%1,%2,%3};"
                 : "+f"(d[0]), "+f"(d[1]), "+f"(d[2]), "+f"(d[3])
                 : "r"(a[0]), "r"(a[1]), "r"(a[2]), "r"(a[3]), "r"(b0), "r"(b1));
}
__device__ __forceinline__ float ex2f(float a) {
    float r; asm("ex2.approx.ftz.f32 %0, %1;" : "=f"(r) : "f"(a)); return r;
}
__device__ __forceinline__ uint32_t pk2(float lo, float hi) {
    __nv_bfloat162 h = __float22bfloat162_rn(make_float2(lo, hi));
    return *(uint32_t*)&h;
}
__device__ __forceinline__ float bflo(uint32_t u) { return __uint_as_float(u << 16); }
__device__ __forceinline__ float bfhi(uint32_t u) { return __uint_as_float(u & 0xffff0000u); }
__device__ __forceinline__ uint32_t pk_split(float a, float b, int low) {
    float ah = __bfloat162float(__float2bfloat16(a));
    float bh = __bfloat162float(__float2bfloat16(b));
    return low ? pk2(a - ah, b - bh) : pk2(ah, bh);
}

// ================= fused prep kernel: ONE task per thread =================
// grid 1280 x 128 = 163840 threads:
//   u in [0, 32768)        : X a-frag task  (wg = u>>5)
//   u in [32768, 98304)    : Y b-frag task  (tn = (u-32768)>>5)
//   u in [98304, 163840)   : B b-frag task
// All boundaries are warp-aligned, so intra-task shfl reductions stay valid.
__global__ void prep_all(const float* __restrict__ ls, const float* __restrict__ x,
                         const float* __restrict__ y, const float* __restrict__ b) {
    int u = blockIdx.x * 128 + threadIdx.x;
    int l = u & 31;
    const float cneg = -ls[0] * LOG2E;

    if (u < 32768) {
        // ---- X a-frags ----
        int t = u;
        int wg = t >> 5;
        int r0 = wg * 16 + (l >> 2), r1 = r0 + 8;
        int c = 2 * (l & 3);
        const float* x0 = x + (size_t)r0 * 32;
        const float* x1 = x + (size_t)r1 * 32;
        float v0[8], v1[8], n0 = 0.f, n1 = 0.f;
#pragma unroll
        for (int kf = 0; kf < 2; kf++)
#pragma unroll
            for (int h = 0; h < 2; h++)
#pragma unroll
                for (int e = 0; e < 2; e++) {
                    int idx = kf * 4 + h * 2 + e;
                    int col = kf * 16 + h * 8 + c + e;
                    v0[idx] = x0[col]; v1[idx] = x1[col];
                    n0 += v0[idx] * v0[idx];
                    n1 += v1[idx] * v1[idx];
                }
        n0 += __shfl_xor_sync(0xffffffffu, n0, 1); n0 += __shfl_xor_sync(0xffffffffu, n0, 2);
        n1 += __shfl_xor_sync(0xffffffffu, n1, 1); n1 += __shfl_xor_sync(0xffffffffu, n1, 2);
        if ((l & 3) == 0) { g_cxn[r0] = cneg * n0; g_cxn[r1] = cneg * n1; }

        uint32_t o[16];
#pragma unroll
        for (int s = 0; s < 2; s++)
#pragma unroll
            for (int kf = 0; kf < 2; kf++)
#pragma unroll
                for (int h = 0; h < 2; h++) {
                    o[s * 8 + kf * 4 + h * 2 + 0] = pk_split(v0[kf * 4 + h * 2], v0[kf * 4 + h * 2 + 1], s);
                    o[s * 8 + kf * 4 + h * 2 + 1] = pk_split(v1[kf * 4 + h * 2], v1[kf * 4 + h * 2 + 1], s);
                }
        uint4* dst = (uint4*)(g_Xf + (size_t)t * 16);
#pragma unroll
        for (int q = 0; q < 4; q++)
            dst[q] = make_uint4(o[4 * q], o[4 * q + 1], o[4 * q + 2], o[4 * q + 3]);
    } else if (u < 98304) {
        // ---- Y b-frags ----
        int t = u - 32768;
        int tn = t >> 5;
        int j = tn * 8 + (l >> 2);
        int c = 2 * (l & 3);
        const float* yr = y + (size_t)j * 32;
        float v[8], n = 0.f;
#pragma unroll
        for (int kf = 0; kf < 2; kf++)
#pragma unroll
            for (int h = 0; h < 2; h++)
#pragma unroll
                for (int e = 0; e < 2; e++) {
                    int idx = kf * 4 + h * 2 + e;
                    v[idx] = yr[kf * 16 + h * 8 + c + e];
                    n += v[idx] * v[idx];
                }
        n += __shfl_xor_sync(0xffffffffu, n, 1); n += __shfl_xor_sync(0xffffffffu, n, 2);
        if ((l & 3) == 0) g_cyn[j] = cneg * n;

        uint32_t o[8];
#pragma unroll
        for (int s = 0; s < 2; s++)
#pragma unroll
            for (int kf = 0; kf < 2; kf++)
#pragma unroll
                for (int h = 0; h < 2; h++)
                    o[s * 4 + kf * 2 + h] = pk_split(v[kf * 4 + h * 2], v[kf * 4 + h * 2 + 1], s);
        uint4* dst = (uint4*)(g_Yf + (size_t)tn * 256 + l * 8);
        dst[0] = make_uint4(o[0], o[1], o[2], o[3]);
        dst[1] = make_uint4(o[4], o[5], o[6], o[7]);
    } else {
        // ---- B b-frags ----
        int t = u - 98304;
        int uu = t >> 5;
        int tile = uu >> 3, fp = uu & 7, kf = fp >> 1, nb2 = fp & 1;
        int c = nb2 * 8 + (l >> 2);
        int jb = tile * 64 + kf * 16 + 2 * (l & 3);
        float p0 = b[(size_t)jb * 16 + c];
        float p1 = b[(size_t)(jb + 1) * 16 + c];
        float p2 = b[(size_t)(jb + 8) * 16 + c];
        float p3 = b[(size_t)(jb + 9) * 16 + c];
        uint32_t h0 = pk_split(p0, p1, 0), h1 = pk_split(p2, p3, 0);
        uint32_t l0 = pk_split(p0, p1, 1), l1 = pk_split(p2, p3, 1);
        *(uint4*)(g_Bf + (size_t)tile * 1024 + fp * 128 + l * 4) = make_uint4(h0, h1, l0, l1);
    }
}

// ================= main kernel: 4 warps x 32 i-rows = 128 i-rows/CTA, 5 CTAs/SM =================
#define SMEM_BYTES 25088

__device__ __forceinline__ void issue_loads(uint32_t smb, int tile, int buf, int tid) {
    const char* gy = (const char*)g_Yf + (size_t)tile * 8192;
    uint32_t dy = smb + buf * 8192;
#pragma unroll
    for (int k = 0; k < 4; k++) cp16(dy + (tid + k * 128) * 16, gy + (size_t)(tid + k * 128) * 16);
    const char* gb = (const char*)g_Bf + (size_t)tile * 4096;
    uint32_t db = smb + 16384 + buf * 4096;
#pragma unroll
    for (int k = 0; k < 2; k++) cp16(db + (tid + k * 128) * 16, gb + (size_t)(tid + k * 128) * 16);
    if (tid < 16) cp16(smb + 24576 + buf * 256 + tid * 16, (const char*)(g_cyn + tile * 64) + tid * 16);
}

__global__ void __launch_bounds__(128, 5)
rbf_main(const float* __restrict__ ls) {
    __shared__ __align__(16) char sm[SMEM_BYTES];
    const uint32_t smb = smem_u32(sm);
    const int tid = threadIdx.x, w = tid >> 5, l = tid & 31;
    const int bidx = blockIdx.x;           // i-block 0..127 (128 rows each)
    const int sl = blockIdx.y;             // j-slice 0..17
    const int tstart = (sl < 4) ? 15 * sl : (60 + 14 * (sl - 4));
    const int tcnt = (sl < 4) ? 15 : 14;
    const int ig = bidx * 128 + w * 32;    // first i-row of this warp's 32

    uint32_t xfA[16], xfB[16];
    {
        const uint4* pA = (const uint4*)(g_Xf + ((size_t)(bidx * 8 + 2 * w) * 32 + l) * 16);
        const uint4* pB = (const uint4*)(g_Xf + ((size_t)(bidx * 8 + 2 * w + 1) * 32 + l) * 16);
#pragma unroll
        for (int q = 0; q < 4; q++) { *(uint4*)(xfA + 4 * q) = pA[q]; *(uint4*)(xfB + 4 * q) = pB[q]; }
    }
    const float cxnA0 = g_cxn[ig + (l >> 2)];
    const float cxnA1 = g_cxn[ig + (l >> 2) + 8];
    const float cxnB0 = g_cxn[ig + (l >> 2) + 16];
    const float cxnB1 = g_cxn[ig + (l >> 2) + 24];
    const float C2 = 2.f * __ldg(ls) * LOG2E;

    float o0A[4] = {0.f, 0.f, 0.f, 0.f}, o1A[4] = {0.f, 0.f, 0.f, 0.f};
    float o0B[4] = {0.f, 0.f, 0.f, 0.f}, o1B[4] = {0.f, 0.f, 0.f, 0.f};

    issue_loads(smb, tstart, 0, tid);
    CP_COMMIT();

    for (int tt = 0; tt < tcnt; tt++) {
        CP_WAIT0();
        __syncthreads();
        if (tt + 1 < tcnt) { issue_loads(smb, tstart + tt + 1, (tt + 1) & 1, tid); CP_COMMIT(); }
        const int buf = tt & 1;
        const char* syb = sm + buf * 8192;
        const char* sbb = sm + 16384 + buf * 4096;
        const char* scy = sm + 24576 + buf * 256;

#pragma unroll
        for (int g = 0; g < 4; g++) {
            uint32_t wahA[4], walA[4], wahB[4], walB[4];
            const char* yb0 = syb + (g * 2) * 1024 + l * 32;
            const char* yb1 = syb + (g * 2 + 1) * 1024 + l * 32;
            uint4 y00 = *(const uint4*)yb0;
            uint4 y01 = *(const uint4*)(yb0 + 16);
            uint4 y10 = *(const uint4*)yb1;
            uint4 y11 = *(const uint4*)(yb1 + 16);

            // ---- GEMM1 burst: 24 MMAs, 4 chains (sA,sB,tA,tB) round-robin ----
            float sA[4] = {0.f, 0.f, 0.f, 0.f}, sB[4] = {0.f, 0.f, 0.f, 0.f};
            float tA[4] = {0.f, 0.f, 0.f, 0.f}, tB[4] = {0.f, 0.f, 0.f, 0.f};
            mma_bf16(sA, xfA + 0,  y00.x, y00.y);
            mma_bf16(sB, xfB + 0,  y00.x, y00.y);
            mma_bf16(tA, xfA + 0,  y10.x, y10.y);
            mma_bf16(tB, xfB + 0,  y10.x, y10.y);
            mma_bf16(sA, xfA + 4,  y00.z, y00.w);
            mma_bf16(sB, xfB + 4,  y00.z, y00.w);
            mma_bf16(tA, xfA + 4,  y10.z, y10.w);
            mma_bf16(tB, xfB + 4,  y10.z, y10.w);
            mma_bf16(sA, xfA + 0,  y01.x, y01.y);
            mma_bf16(sB, xfB + 0,  y01.x, y01.y);
            mma_bf16(tA, xfA + 0,  y11.x, y11.y);
            mma_bf16(tB, xfB + 0,  y11.x, y11.y);
            mma_bf16(sA, xfA + 4,  y01.z, y01.w);
            mma_bf16(sB, xfB + 4,  y01.z, y01.w);
            mma_bf16(tA, xfA + 4,  y11.z, y11.w);
            mma_bf16(tB, xfB + 4,  y11.z, y11.w);
            mma_bf16(sA, xfA + 8,  y00.x, y00.y);
            mma_bf16(sB, xfB + 8,  y00.x, y00.y);
            mma_bf16(tA, xfA + 8,  y10.x, y10.y);
            mma_bf16(tB, xfB + 8,  y10.x, y10.y);
            mma_bf16(sA, xfA + 12, y00.z, y00.w);
            mma_bf16(sB, xfB + 12, y00.z, y00.w);
            mma_bf16(tA, xfA + 12, y10.z, y10.w);
            mma_bf16(tB, xfB + 12, y10.z, y10.w);

            // ---- epilogue h0 ----
            {
                float2 cy = *(const float2*)(scy + (g * 2) * 32 + (l & 3) * 8);
                float w0 = ex2f(fminf(fmaf(C2, sA[0], cxnA0 + cy.x), 0.f));
                float w1 = ex2f(fminf(fmaf(C2, sA[1], cxnA0 + cy.y), 0.f));
                float w2 = ex2f(fminf(fmaf(C2, sA[2], cxnA1 + cy.x), 0.f));
                float w3 = ex2f(fminf(fmaf(C2, sA[3], cxnA1 + cy.y), 0.f));
                uint32_t h01 = pk2(w0, w1), h23 = pk2(w2, w3);
                wahA[0] = h01; wahA[1] = h23;
                walA[0] = pk2(w0 - bflo(h01), w1 - bfhi(h01));
                walA[1] = pk2(w2 - bflo(h23), w3 - bfhi(h23));
                float v0 = ex2f(fminf(fmaf(C2, sB[0], cxnB0 + cy.x), 0.f));
                float v1 = ex2f(fminf(fmaf(C2, sB[1], cxnB0 + cy.y), 0.f));
                float v2 = ex2f(fminf(fmaf(C2, sB[2], cxnB1 + cy.x), 0.f));
                float v3 = ex2f(fminf(fmaf(C2, sB[3], cxnB1 + cy.y), 0.f));
                uint32_t g01 = pk2(v0, v1), g23 = pk2(v2, v3);
                wahB[0] = g01; wahB[1] = g23;
                walB[0] = pk2(v0 - bflo(g01), v1 - bfhi(g01));
                walB[1] = pk2(v2 - bflo(g23), v3 - bfhi(g23));
            }
            // ---- epilogue h1 ----
            {
                float2 cy = *(const float2*)(scy + (g * 2 + 1) * 32 + (l & 3) * 8);
                float w0 = ex2f(fminf(fmaf(C2, tA[0], cxnA0 + cy.x), 0.f));
                float w1 = ex2f(fminf(fmaf(C2, tA[1], cxnA0 + cy.y), 0.f));
                float w2 = ex2f(fminf(fmaf(C2, tA[2], cxnA1 + cy.x), 0.f));
                float w3 = ex2f(fminf(fmaf(C2, tA[3], cxnA1 + cy.y), 0.f));
                uint32_t h01 = pk2(w0, w1), h23 = pk2(w2, w3);
                wahA[2] = h01; wahA[3] = h23;
                walA[2] = pk2(w0 - bflo(h01), w1 - bfhi(h01));
                walA[3] = pk2(w2 - bflo(h23), w3 - bfhi(h23));
                float v0 = ex2f(fminf(fmaf(C2, tB[0], cxnB0 + cy.x), 0.f));
                float v1 = ex2f(fminf(fmaf(C2, tB[1], cxnB0 + cy.y), 0.f));
                float v2 = ex2f(fminf(fmaf(C2, tB[2], cxnB1 + cy.x), 0.f));
                float v3 = ex2f(fminf(fmaf(C2, tB[3], cxnB1 + cy.y), 0.f));
                uint32_t g01 = pk2(v0, v1), g23 = pk2(v2, v3);
                wahB[2] = g01; wahB[3] = g23;
                walB[2] = pk2(v0 - bflo(g01), v1 - bfhi(g01));
                walB[3] = pk2(v2 - bflo(g23), v3 - bfhi(g23));
            }
            // ---- GEMM2: 4 accumulator chains round-robin ----
            uint4 b0 = *(const uint4*)(sbb + (g * 2) * 512 + l * 16);
            uint4 b1 = *(const uint4*)(sbb + (g * 2 + 1) * 512 + l * 16);
            mma_bf16(o0A, wahA, b0.x, b0.y);
            mma_bf16(o0B, wahB, b0.x, b0.y);
            mma_bf16(o1A, wahA, b1.x, b1.y);
            mma_bf16(o1B, wahB, b1.x, b1.y);
            mma_bf16(o0A, wahA, b0.z, b0.w);
            mma_bf16(o0B, wahB, b0.z, b0.w);
            mma_bf16(o1A, wahA, b1.z, b1.w);
            mma_bf16(o1B, wahB, b1.z, b1.w);
            mma_bf16(o0A, walA, b0.x, b0.y);
            mma_bf16(o0B, walB, b0.x, b0.y);
            mma_bf16(o1A, walA, b1.x, b1.y);
            mma_bf16(o1B, walB, b1.x, b1.y);
        }
    }

    // partial write: slice-local buffer
    float* op = g_Op + (size_t)sl * (NP * 16);
    const int cb = 2 * (l & 3);
    const int rA = ig + (l >> 2), rB = rA + 16;
    *(float2*)(op + (size_t)rA * 16 + cb)            = make_float2(o0A[0], o0A[1]);
    *(float2*)(op + (size_t)rA * 16 + 8 + cb)        = make_float2(o1A[0], o1A[1]);
    *(float2*)(op + (size_t)(rA + 8) * 16 + cb)      = make_float2(o0A[2], o0A[3]);
    *(float2*)(op + (size_t)(rA + 8) * 16 + 8 + cb)  = make_float2(o1A[2], o1A[3]);
    *(float2*)(op + (size_t)rB * 16 + cb)            = make_float2(o0B[0], o0B[1]);
    *(float2*)(op + (size_t)rB * 16 + 8 + cb)        = make_float2(o1B[0], o1B[1]);
    *(float2*)(op + (size_t)(rB + 8) * 16 + cb)      = make_float2(o0B[2], o0B[3]);
    *(float2*)(op + (size_t)(rB + 8) * 16 + 8 + cb)  = make_float2(o1B[2], o1B[3]);
}

// ================= deterministic slice reduction =================
__global__ void reduce_k(float* __restrict__ out) {
    int idx = blockIdx.x * 256 + threadIdx.x;
    float4 o = ((const float4*)g_Op)[idx];
#pragma unroll
    for (int s = 1; s < NSL; s++) {
        float4 v = ((const float4*)(g_Op + (size_t)s * NP * 16))[idx];
        o.x += v.x; o.y += v.y; o.z += v.z; o.w += v.w;   // fixed slice order
    }
    ((float4*)out)[idx] = o;
}

extern "C" void kernel_launch(void* const* d_in, const int* in_sizes, int n_in,
                              void* d_out, int out_size) {
    const float* ls = (const float*)d_in[0];
    const float* x  = (const float*)d_in[1];
    const float* y  = (const float*)d_in[2];
    const float* b  = (const float*)d_in[3];
    float* out = (float*)d_out;

    prep_all<<<1280, 128>>>(ls, x, y, b);
    rbf_main<<<dim3(128, NSL), 128>>>(ls);
    reduce_k<<<256, 256>>>(out);
}